// round 8
// baseline (speedup 1.0000x reference)
#include <cuda_runtime.h>
#include <cstdint>

#define TT   1024
#define BB   512
#define HD   64
#define GG   192   // 3*HD
#define NB   4     // batches per CTA
#define NTH  576   // 3 task groups * 192 rows
#define NCTA (BB / NB)

typedef unsigned long long ull;

// ---------------- helpers ----------------

__device__ __forceinline__ ull fma2(ull a, ull b, ull c) {
    ull d;
    asm("fma.rn.f32x2 %0, %1, %2, %3;" : "=l"(d) : "l"(a), "l"(b), "l"(c));
    return d;
}

__device__ __forceinline__ ull add2(ull a, ull b) {
    ull d;
    asm("add.rn.f32x2 %0, %1, %2;" : "=l"(d) : "l"(a), "l"(b));
    return d;
}

__device__ __forceinline__ ull pack2(float a, float b) {
    ull r;
    asm("mov.b64 %0, {%1, %2};" : "=l"(r) : "f"(a), "f"(b));
    return r;
}

__device__ __forceinline__ float hadd2(ull v) {
    float x, y;
    asm("mov.b64 {%0, %1}, %2;" : "=f"(x), "=f"(y) : "l"(v));
    return x + y;
}

__device__ __forceinline__ float tanh_fast(float x) {
    float y;
    asm("tanh.approx.f32 %0, %1;" : "=f"(y) : "f"(x));
    return y;
}

__device__ __forceinline__ float sigf(float x) {
    // sigmoid(x) = 0.5*tanh(0.5x) + 0.5  (single MUFU)
    return fmaf(0.5f, tanh_fast(0.5f * x), 0.5f);
}

// ---------------- fused 2-layer GRU ----------------
// Pipeline skew 1: iteration i computes layer0 step t=i and layer1 step t=i-1.
// Task groups (192 threads each):
//   task0: gh0 = W_hh0 . p[i-1]  (+ gx0 from x, 3-wide)
//   task1: gx1 = W_ih1 . p[i-1]
//   task2: gh1 = W_hh1 . q[i-2]
// Gate phase: tid<256 -> layer0 gates (p update); tid<512 -> layer1 gates
// (q update + seq_out); tid 512..523 -> x prefetch (t+2).
__global__ void __launch_bounds__(NTH, 1) gru_fused(
    const float* __restrict__ x,
    const float* __restrict__ Wih0, const float* __restrict__ Whh0,
    const float* __restrict__ bih0, const float* __restrict__ bhh0,
    const float* __restrict__ Wih1, const float* __restrict__ Whh1,
    const float* __restrict__ bih1, const float* __restrict__ bhh1,
    float* __restrict__ seq_out, float* __restrict__ fin)
{
    __shared__ __align__(16) float p_state[NB][HD];   // layer0 hidden
    __shared__ __align__(16) float q_state[NB][HD];   // layer1 hidden
    __shared__ float a0s[NB][GG];   // gx0 + bih0
    __shared__ float h0s[NB][GG];   // gh0 + bhh0
    __shared__ float a1s[NB][GG];   // gx1 + bih1
    __shared__ float h1s[NB][GG];   // gh1 + bhh1
    __shared__ float xr[4][NB][3];  // x ring, 2-step prefetch

    const int tid  = threadIdx.x;
    const int b0   = blockIdx.x * NB;
    const int task = tid / GG;      // 0,1,2 (warp-uniform: 192 = 6 warps)
    const int row  = tid % GG;

    const float* Wmat = (task == 0) ? Whh0 : (task == 1) ? Wih1 : Whh1;
    const float* bvec = (task == 0) ? bhh0 : (task == 1) ? bih1 : bhh1;

    // one weight row per thread, packed f32x2 (rows are 256B-aligned)
    ull w[32];
    const ull* wrow = (const ull*)(Wmat + row * HD);
#pragma unroll
    for (int i2 = 0; i2 < 32; i2++) w[i2] = wrow[i2];
    const float bias = bvec[row];

    // task0 extras: layer0 input projection (IN=3)
    float wi0 = 0.f, wi1 = 0.f, wi2 = 0.f, bi = 0.f;
    if (task == 0) {
        wi0 = Wih0[row * 3 + 0];
        wi1 = Wih0[row * 3 + 1];
        wi2 = Wih0[row * 3 + 2];
        bi  = bih0[row];
    }

    for (int i2 = tid; i2 < NB * HD; i2 += NTH) {
        ((float*)p_state)[i2] = 0.f;
        ((float*)q_state)[i2] = 0.f;
    }
    // prefetch x for t = 0, 1
    if (tid < 2 * NB * 3) {
        int t = tid / (NB * 3);
        int rr = tid % (NB * 3);
        int b = rr / 3, f = rr % 3;
        xr[t][b][f] = x[(size_t)(b0 + b) * TT * 3 + t * 3 + f];
    }

    float hprev = 0.f;  // per-gate-thread recurrent lane (p for tid<256, q for tid<512)
    __syncthreads();

    const float* src = (task == 2) ? &q_state[0][0] : &p_state[0][0];

    for (int i = 0; i <= TT; i++) {
        const int sl = i & 3;

        // ---- phase 1: 64-wide dot per (row, b) ----
        ull acc0[NB], acc1[NB];
#pragma unroll
        for (int b = 0; b < NB; b++) { acc0[b] = pack2(bias, 0.f); acc1[b] = 0ull; }
#pragma unroll
        for (int k = 0; k < 16; k++) {
#pragma unroll
            for (int b = 0; b < NB; b++) {
                ulonglong2 hp = ((const ulonglong2*)(src + b * HD))[k];
                acc0[b] = fma2(hp.x, w[2 * k],     acc0[b]);
                acc1[b] = fma2(hp.y, w[2 * k + 1], acc1[b]);
            }
        }
        if (task == 0) {
#pragma unroll
            for (int b = 0; b < NB; b++) {
                h0s[b][row] = hadd2(add2(acc0[b], acc1[b]));
                a0s[b][row] = fmaf(wi2, xr[sl][b][2],
                              fmaf(wi1, xr[sl][b][1],
                              fmaf(wi0, xr[sl][b][0], bi)));
            }
        } else if (task == 1) {
#pragma unroll
            for (int b = 0; b < NB; b++)
                a1s[b][row] = hadd2(add2(acc0[b], acc1[b]));
        } else {
#pragma unroll
            for (int b = 0; b < NB; b++)
                h1s[b][row] = hadd2(add2(acc0[b], acc1[b]));
        }
        __syncthreads();

        // ---- phase 2: gates + prefetch ----
        if (tid < 256) {
            if (i < TT) {       // layer0 step t=i
                int b = tid >> 6, j = tid & 63;
                float r = sigf(a0s[b][j]      + h0s[b][j]);
                float z = sigf(a0s[b][j + 64] + h0s[b][j + 64]);
                float n = tanh_fast(fmaf(r, h0s[b][j + 128], a0s[b][j + 128]));
                float h = fmaf(z, hprev - n, n);
                hprev = h;
                p_state[b][j] = h;
            }
        } else if (tid < 512) {
            if (i >= 1) {       // layer1 step t=i-1
                int b = (tid - 256) >> 6, j = tid & 63;
                float r = sigf(a1s[b][j]      + h1s[b][j]);
                float z = sigf(a1s[b][j + 64] + h1s[b][j + 64]);
                float n = tanh_fast(fmaf(r, h1s[b][j + 128], a1s[b][j + 128]));
                float h = fmaf(z, hprev - n, n);
                hprev = h;
                q_state[b][j] = h;
                seq_out[((size_t)(b0 + b) * TT + (i - 1)) * HD + j] = h;
                if (i == TT) fin[(b0 + b) * HD + j] = h;
            }
        } else if (tid < 512 + NB * 3) {
            int t2 = i + 2;
            if (t2 < TT) {
                int rr = tid - 512;
                int b = rr / 3, f = rr % 3;
                xr[t2 & 3][b][f] = x[(size_t)(b0 + b) * TT * 3 + t2 * 3 + f];
            }
        }
        __syncthreads();
    }
}

// ---------------- launch ----------------

extern "C" void kernel_launch(void* const* d_in, const int* in_sizes, int n_in,
                              void* d_out, int out_size)
{
    const float* x    = (const float*)d_in[0];
    const float* Wih0 = (const float*)d_in[1];
    const float* Whh0 = (const float*)d_in[2];
    const float* bih0 = (const float*)d_in[3];
    const float* bhh0 = (const float*)d_in[4];
    const float* Wih1 = (const float*)d_in[5];
    const float* Whh1 = (const float*)d_in[6];
    const float* bih1 = (const float*)d_in[7];
    const float* bhh1 = (const float*)d_in[8];

    float* seq_out = (float*)d_out;
    float* fin     = seq_out + (size_t)BB * TT * HD;

    gru_fused<<<NCTA, NTH>>>(x, Wih0, Whh0, bih0, bhh0,
                             Wih1, Whh1, bih1, bhh1, seq_out, fin);
}

// round 10
// speedup vs baseline: 1.0055x; 1.0055x over previous
#include <cuda_runtime.h>
#include <cstdint>

#define TT   1024
#define BB   512
#define HD   64
#define GG   192   // 3*HD
#define NB   4     // batches per CTA
#define NTH  576   // 3 task groups * 192 rows
#define NCTA (BB / NB)

typedef unsigned long long ull;

// ---------------- helpers ----------------

__device__ __forceinline__ ull fma2(ull a, ull b, ull c) {
    ull d;
    asm("fma.rn.f32x2 %0, %1, %2, %3;" : "=l"(d) : "l"(a), "l"(b), "l"(c));
    return d;
}

__device__ __forceinline__ ull add2(ull a, ull b) {
    ull d;
    asm("add.rn.f32x2 %0, %1, %2;" : "=l"(d) : "l"(a), "l"(b));
    return d;
}

__device__ __forceinline__ ull pack2(float a, float b) {
    ull r;
    asm("mov.b64 %0, {%1, %2};" : "=l"(r) : "f"(a), "f"(b));
    return r;
}

__device__ __forceinline__ float hadd2(ull v) {
    float x, y;
    asm("mov.b64 {%0, %1}, %2;" : "=f"(x), "=f"(y) : "l"(v));
    return x + y;
}

__device__ __forceinline__ float tanh_fast(float x) {
    float y;
    asm("tanh.approx.f32 %0, %1;" : "=f"(y) : "f"(x));
    return y;
}

__device__ __forceinline__ float sigf(float x) {
    // sigmoid(x) = 0.5*tanh(0.5x) + 0.5  (single MUFU)
    return fmaf(0.5f, tanh_fast(0.5f * x), 0.5f);
}

// ---------------- fused 2-layer GRU ----------------
// Pipeline skew 1: iteration i computes layer0 step t=i and layer1 step t=i-1.
// Task groups (192 threads each):
//   task0: gh0 = W_hh0 . p[i-1]  (+ gx0 from x, 3-wide)
//   task1: gx1 = W_ih1 . p[i-1]
//   task2: gh1 = W_hh1 . q[i-2]
// Gate phase: tid<256 -> layer0 gates (p update); tid<512 -> layer1 gates
// (q update + seq_out); tid 512..523 -> x prefetch (t+2).
__global__ void __launch_bounds__(NTH, 1) gru_fused(
    const float* __restrict__ x,
    const float* __restrict__ Wih0, const float* __restrict__ Whh0,
    const float* __restrict__ bih0, const float* __restrict__ bhh0,
    const float* __restrict__ Wih1, const float* __restrict__ Whh1,
    const float* __restrict__ bih1, const float* __restrict__ bhh1,
    float* __restrict__ seq_out, float* __restrict__ fin)
{
    __shared__ __align__(16) float p_state[NB][HD];   // layer0 hidden
    __shared__ __align__(16) float q_state[NB][HD];   // layer1 hidden
    __shared__ float a0s[NB][GG];   // gx0 + bih0
    __shared__ float h0s[NB][GG];   // gh0 + bhh0
    __shared__ float a1s[NB][GG];   // gx1 + bih1
    __shared__ float h1s[NB][GG];   // gh1 + bhh1
    __shared__ float xr[4][NB][3];  // x ring, 2-step prefetch

    const int tid  = threadIdx.x;
    const int b0   = blockIdx.x * NB;
    const int task = tid / GG;      // 0,1,2 (warp-uniform: 192 = 6 warps)
    const int row  = tid % GG;

    const float* Wmat = (task == 0) ? Whh0 : (task == 1) ? Wih1 : Whh1;
    const float* bvec = (task == 0) ? bhh0 : (task == 1) ? bih1 : bhh1;

    // one weight row per thread, packed f32x2 (rows are 256B-aligned)
    ull w[32];
    const ull* wrow = (const ull*)(Wmat + row * HD);
#pragma unroll
    for (int i2 = 0; i2 < 32; i2++) w[i2] = wrow[i2];
    const float bias = bvec[row];

    // task0 extras: layer0 input projection (IN=3)
    float wi0 = 0.f, wi1 = 0.f, wi2 = 0.f, bi = 0.f;
    if (task == 0) {
        wi0 = Wih0[row * 3 + 0];
        wi1 = Wih0[row * 3 + 1];
        wi2 = Wih0[row * 3 + 2];
        bi  = bih0[row];
    }

    for (int i2 = tid; i2 < NB * HD; i2 += NTH) {
        ((float*)p_state)[i2] = 0.f;
        ((float*)q_state)[i2] = 0.f;
    }
    // prefetch x for t = 0, 1
    if (tid < 2 * NB * 3) {
        int t = tid / (NB * 3);
        int rr = tid % (NB * 3);
        int b = rr / 3, f = rr % 3;
        xr[t][b][f] = x[(size_t)(b0 + b) * TT * 3 + t * 3 + f];
    }

    float hprev = 0.f;  // per-gate-thread recurrent lane (p for tid<256, q for tid<512)
    __syncthreads();

    const float* src = (task == 2) ? &q_state[0][0] : &p_state[0][0];

    for (int i = 0; i <= TT; i++) {
        const int sl = i & 3;

        // ---- phase 1: 64-wide dot per (row, b) ----
        ull acc0[NB], acc1[NB];
#pragma unroll
        for (int b = 0; b < NB; b++) { acc0[b] = pack2(bias, 0.f); acc1[b] = 0ull; }
#pragma unroll
        for (int k = 0; k < 16; k++) {
#pragma unroll
            for (int b = 0; b < NB; b++) {
                ulonglong2 hp = ((const ulonglong2*)(src + b * HD))[k];
                acc0[b] = fma2(hp.x, w[2 * k],     acc0[b]);
                acc1[b] = fma2(hp.y, w[2 * k + 1], acc1[b]);
            }
        }
        if (task == 0) {
#pragma unroll
            for (int b = 0; b < NB; b++) {
                h0s[b][row] = hadd2(add2(acc0[b], acc1[b]));
                a0s[b][row] = fmaf(wi2, xr[sl][b][2],
                              fmaf(wi1, xr[sl][b][1],
                              fmaf(wi0, xr[sl][b][0], bi)));
            }
        } else if (task == 1) {
#pragma unroll
            for (int b = 0; b < NB; b++)
                a1s[b][row] = hadd2(add2(acc0[b], acc1[b]));
        } else {
#pragma unroll
            for (int b = 0; b < NB; b++)
                h1s[b][row] = hadd2(add2(acc0[b], acc1[b]));
        }
        __syncthreads();

        // ---- phase 2: gates + prefetch ----
        if (tid < 256) {
            if (i < TT) {       // layer0 step t=i
                int b = tid >> 6, j = tid & 63;
                float r = sigf(a0s[b][j]      + h0s[b][j]);
                float z = sigf(a0s[b][j + 64] + h0s[b][j + 64]);
                float n = tanh_fast(fmaf(r, h0s[b][j + 128], a0s[b][j + 128]));
                float h = fmaf(z, hprev - n, n);
                hprev = h;
                p_state[b][j] = h;
            }
        } else if (tid < 512) {
            if (i >= 1) {       // layer1 step t=i-1
                int b = (tid - 256) >> 6, j = tid & 63;
                float r = sigf(a1s[b][j]      + h1s[b][j]);
                float z = sigf(a1s[b][j + 64] + h1s[b][j + 64]);
                float n = tanh_fast(fmaf(r, h1s[b][j + 128], a1s[b][j + 128]));
                float h = fmaf(z, hprev - n, n);
                hprev = h;
                q_state[b][j] = h;
                seq_out[((size_t)(b0 + b) * TT + (i - 1)) * HD + j] = h;
                if (i == TT) fin[(b0 + b) * HD + j] = h;
            }
        } else if (tid < 512 + NB * 3) {
            int t2 = i + 2;
            if (t2 < TT) {
                int rr = tid - 512;
                int b = rr / 3, f = rr % 3;
                xr[t2 & 3][b][f] = x[(size_t)(b0 + b) * TT * 3 + t2 * 3 + f];
            }
        }
        __syncthreads();
    }
}

// ---------------- launch ----------------

extern "C" void kernel_launch(void* const* d_in, const int* in_sizes, int n_in,
                              void* d_out, int out_size)
{
    const float* x    = (const float*)d_in[0];
    const float* Wih0 = (const float*)d_in[1];
    const float* Whh0 = (const float*)d_in[2];
    const float* bih0 = (const float*)d_in[3];
    const float* bhh0 = (const float*)d_in[4];
    const float* Wih1 = (const float*)d_in[5];
    const float* Whh1 = (const float*)d_in[6];
    const float* bih1 = (const float*)d_in[7];
    const float* bhh1 = (const float*)d_in[8];

    float* seq_out = (float*)d_out;
    float* fin     = seq_out + (size_t)BB * TT * HD;

    gru_fused<<<NCTA, NTH>>>(x, Wih0, Whh0, bih0, bhh0,
                             Wih1, Whh1, bih1, bhh1, seq_out, fin);
}

// round 13
// speedup vs baseline: 1.0200x; 1.0144x over previous
#include <cuda_runtime.h>
#include <cstdint>

#define TT   1024
#define BB   512
#define HD   64
#define GG   192   // 3*HD
#define NB   4     // batches per CTA
#define NTH  576   // 3 task groups * 192 rows
#define NCTA (BB / NB)

typedef unsigned long long ull;

// ---------------- helpers ----------------

__device__ __forceinline__ ull fma2(ull a, ull b, ull c) {
    ull d;
    asm("fma.rn.f32x2 %0, %1, %2, %3;" : "=l"(d) : "l"(a), "l"(b), "l"(c));
    return d;
}

__device__ __forceinline__ ull add2(ull a, ull b) {
    ull d;
    asm("add.rn.f32x2 %0, %1, %2;" : "=l"(d) : "l"(a), "l"(b));
    return d;
}

__device__ __forceinline__ ull pack2(float a, float b) {
    ull r;
    asm("mov.b64 %0, {%1, %2};" : "=l"(r) : "f"(a), "f"(b));
    return r;
}

__device__ __forceinline__ float hadd2(ull v) {
    float x, y;
    asm("mov.b64 {%0, %1}, %2;" : "=f"(x), "=f"(y) : "l"(v));
    return x + y;
}

__device__ __forceinline__ float tanh_fast(float x) {
    float y;
    asm("tanh.approx.f32 %0, %1;" : "=f"(y) : "f"(x));
    return y;
}

__device__ __forceinline__ float sigf(float x) {
    // sigmoid(x) = 0.5*tanh(0.5x) + 0.5  (single MUFU)
    return fmaf(0.5f, tanh_fast(0.5f * x), 0.5f);
}

// ---------------- fused 2-layer GRU ----------------
// Pipeline skew 1: iteration i computes layer0 step t=i and layer1 step t=i-1.
// Task groups (192 threads each):
//   task0: gh0 = W_hh0 . p[i-1]  (+ gx0 from x, 3-wide)
//   task1: gx1 = W_ih1 . p[i-1]
//   task2: gh1 = W_hh1 . q[i-2]
// Gate phase: tid<256 -> layer0 gates (p update); tid<512 -> layer1 gates
// (q update + seq_out); tid 512..523 -> x prefetch (t+2).
__global__ void __launch_bounds__(NTH, 1) gru_fused(
    const float* __restrict__ x,
    const float* __restrict__ Wih0, const float* __restrict__ Whh0,
    const float* __restrict__ bih0, const float* __restrict__ bhh0,
    const float* __restrict__ Wih1, const float* __restrict__ Whh1,
    const float* __restrict__ bih1, const float* __restrict__ bhh1,
    float* __restrict__ seq_out, float* __restrict__ fin)
{
    __shared__ __align__(16) float p_state[NB][HD];   // layer0 hidden
    __shared__ __align__(16) float q_state[NB][HD];   // layer1 hidden
    __shared__ float a0s[NB][GG];   // gx0 + bih0
    __shared__ float h0s[NB][GG];   // gh0 + bhh0
    __shared__ float a1s[NB][GG];   // gx1 + bih1
    __shared__ float h1s[NB][GG];   // gh1 + bhh1
    __shared__ float xr[4][NB][3];  // x ring, 2-step prefetch

    const int tid  = threadIdx.x;
    const int b0   = blockIdx.x * NB;
    const int task = tid / GG;      // 0,1,2 (warp-uniform: 192 = 6 warps)
    const int row  = tid % GG;

    const float* Wmat = (task == 0) ? Whh0 : (task == 1) ? Wih1 : Whh1;
    const float* bvec = (task == 0) ? bhh0 : (task == 1) ? bih1 : bhh1;

    // one weight row per thread, packed f32x2 (rows are 256B-aligned)
    ull w[32];
    const ull* wrow = (const ull*)(Wmat + row * HD);
#pragma unroll
    for (int i2 = 0; i2 < 32; i2++) w[i2] = wrow[i2];
    const float bias = bvec[row];

    // task0 extras: layer0 input projection (IN=3)
    float wi0 = 0.f, wi1 = 0.f, wi2 = 0.f, bi = 0.f;
    if (task == 0) {
        wi0 = Wih0[row * 3 + 0];
        wi1 = Wih0[row * 3 + 1];
        wi2 = Wih0[row * 3 + 2];
        bi  = bih0[row];
    }

    for (int i2 = tid; i2 < NB * HD; i2 += NTH) {
        ((float*)p_state)[i2] = 0.f;
        ((float*)q_state)[i2] = 0.f;
    }
    // prefetch x for t = 0, 1
    if (tid < 2 * NB * 3) {
        int t = tid / (NB * 3);
        int rr = tid % (NB * 3);
        int b = rr / 3, f = rr % 3;
        xr[t][b][f] = x[(size_t)(b0 + b) * TT * 3 + t * 3 + f];
    }

    float hprev = 0.f;  // per-gate-thread recurrent lane (p for tid<256, q for tid<512)
    __syncthreads();

    const float* src = (task == 2) ? &q_state[0][0] : &p_state[0][0];

    for (int i = 0; i <= TT; i++) {
        const int sl = i & 3;

        // ---- phase 1: 64-wide dot per (row, b) ----
        ull acc0[NB], acc1[NB];
#pragma unroll
        for (int b = 0; b < NB; b++) { acc0[b] = pack2(bias, 0.f); acc1[b] = 0ull; }
#pragma unroll
        for (int k = 0; k < 16; k++) {
#pragma unroll
            for (int b = 0; b < NB; b++) {
                ulonglong2 hp = ((const ulonglong2*)(src + b * HD))[k];
                acc0[b] = fma2(hp.x, w[2 * k],     acc0[b]);
                acc1[b] = fma2(hp.y, w[2 * k + 1], acc1[b]);
            }
        }
        if (task == 0) {
#pragma unroll
            for (int b = 0; b < NB; b++) {
                h0s[b][row] = hadd2(add2(acc0[b], acc1[b]));
                a0s[b][row] = fmaf(wi2, xr[sl][b][2],
                              fmaf(wi1, xr[sl][b][1],
                              fmaf(wi0, xr[sl][b][0], bi)));
            }
        } else if (task == 1) {
#pragma unroll
            for (int b = 0; b < NB; b++)
                a1s[b][row] = hadd2(add2(acc0[b], acc1[b]));
        } else {
#pragma unroll
            for (int b = 0; b < NB; b++)
                h1s[b][row] = hadd2(add2(acc0[b], acc1[b]));
        }
        __syncthreads();

        // ---- phase 2: gates + prefetch ----
        if (tid < 256) {
            if (i < TT) {       // layer0 step t=i
                int b = tid >> 6, j = tid & 63;
                float r = sigf(a0s[b][j]      + h0s[b][j]);
                float z = sigf(a0s[b][j + 64] + h0s[b][j + 64]);
                float n = tanh_fast(fmaf(r, h0s[b][j + 128], a0s[b][j + 128]));
                float h = fmaf(z, hprev - n, n);
                hprev = h;
                p_state[b][j] = h;
            }
        } else if (tid < 512) {
            if (i >= 1) {       // layer1 step t=i-1
                int b = (tid - 256) >> 6, j = tid & 63;
                float r = sigf(a1s[b][j]      + h1s[b][j]);
                float z = sigf(a1s[b][j + 64] + h1s[b][j + 64]);
                float n = tanh_fast(fmaf(r, h1s[b][j + 128], a1s[b][j + 128]));
                float h = fmaf(z, hprev - n, n);
                hprev = h;
                q_state[b][j] = h;
                seq_out[((size_t)(b0 + b) * TT + (i - 1)) * HD + j] = h;
                if (i == TT) fin[(b0 + b) * HD + j] = h;
            }
        } else if (tid < 512 + NB * 3) {
            int t2 = i + 2;
            if (t2 < TT) {
                int rr = tid - 512;
                int b = rr / 3, f = rr % 3;
                xr[t2 & 3][b][f] = x[(size_t)(b0 + b) * TT * 3 + t2 * 3 + f];
            }
        }
        __syncthreads();
    }
}

// ---------------- launch ----------------

extern "C" void kernel_launch(void* const* d_in, const int* in_sizes, int n_in,
                              void* d_out, int out_size)
{
    const float* x    = (const float*)d_in[0];
    const float* Wih0 = (const float*)d_in[1];
    const float* Whh0 = (const float*)d_in[2];
    const float* bih0 = (const float*)d_in[3];
    const float* bhh0 = (const float*)d_in[4];
    const float* Wih1 = (const float*)d_in[5];
    const float* Whh1 = (const float*)d_in[6];
    const float* bih1 = (const float*)d_in[7];
    const float* bhh1 = (const float*)d_in[8];

    float* seq_out = (float*)d_out;
    float* fin     = seq_out + (size_t)BB * TT * HD;

    gru_fused<<<NCTA, NTH>>>(x, Wih0, Whh0, bih0, bhh0,
                             Wih1, Whh1, bih1, bhh1, seq_out, fin);
}

// round 14
// speedup vs baseline: 1.0599x; 1.0391x over previous
#include <cuda_runtime.h>
#include <cstdint>

#define TT   1024
#define BB   512
#define HD   64
#define GG   192   // 3*HD
#define NB   4     // batches per CTA
#define NTH  576   // 3 task groups * 192 rows
#define NCTA (BB / NB)

typedef unsigned long long ull;

// ---------------- helpers ----------------

// In-place packed FMA: acc = a*b + acc  (keeps acc in one aligned reg pair,
// no operand-marshaling MOVs even under register pressure).
__device__ __forceinline__ void fma2_acc(ull& acc, ull a, ull b) {
    asm("fma.rn.f32x2 %0, %1, %2, %0;" : "+l"(acc) : "l"(a), "l"(b));
}

__device__ __forceinline__ ull add2(ull a, ull b) {
    ull d;
    asm("add.rn.f32x2 %0, %1, %2;" : "=l"(d) : "l"(a), "l"(b));
    return d;
}

__device__ __forceinline__ ull pack2(float a, float b) {
    ull r;
    asm("mov.b64 %0, {%1, %2};" : "=l"(r) : "f"(a), "f"(b));
    return r;
}

__device__ __forceinline__ float hadd2(ull v) {
    float x, y;
    asm("mov.b64 {%0, %1}, %2;" : "=f"(x), "=f"(y) : "l"(v));
    return x + y;
}

__device__ __forceinline__ float tanh_fast(float x) {
    float y;
    asm("tanh.approx.f32 %0, %1;" : "=f"(y) : "f"(x));
    return y;
}

__device__ __forceinline__ float sigf(float x) {
    // sigmoid(x) = 0.5*tanh(0.5x) + 0.5  (single MUFU)
    return fmaf(0.5f, tanh_fast(0.5f * x), 0.5f);
}

// ---------------- fused 2-layer GRU ----------------
// Pipeline skew 1: iteration i computes layer0 step t=i and layer1 step t=i-1.
// Task groups (192 threads each):
//   task0: gh0 = W_hh0 . p[i-1]  (+ gx0 from x, 3-wide)
//   task1: gx1 = W_ih1 . p[i-1]
//   task2: gh1 = W_hh1 . q[i-2]
__global__ void __launch_bounds__(NTH, 1) gru_fused(
    const float* __restrict__ x,
    const float* __restrict__ Wih0, const float* __restrict__ Whh0,
    const float* __restrict__ bih0, const float* __restrict__ bhh0,
    const float* __restrict__ Wih1, const float* __restrict__ Whh1,
    const float* __restrict__ bih1, const float* __restrict__ bhh1,
    float* __restrict__ seq_out, float* __restrict__ fin)
{
    __shared__ __align__(16) float p_state[NB][HD];   // layer0 hidden
    __shared__ __align__(16) float q_state[NB][HD];   // layer1 hidden
    __shared__ float a0s[NB][GG];   // gx0 + bih0
    __shared__ float h0s[NB][GG];   // gh0 + bhh0
    __shared__ float a1s[NB][GG];   // gx1 + bih1
    __shared__ float h1s[NB][GG];   // gh1 + bhh1
    __shared__ float xr[4][NB][3];  // x ring, 2-step prefetch

    const int tid  = threadIdx.x;
    const int b0   = blockIdx.x * NB;
    const int task = tid / GG;      // 0,1,2 (warp-uniform: 192 = 6 warps)
    const int row  = tid % GG;

    const float* Wmat = (task == 0) ? Whh0 : (task == 1) ? Wih1 : Whh1;
    const float* bvec = (task == 0) ? bhh0 : (task == 1) ? bih1 : bhh1;

    // one weight row per thread, packed f32x2 (rows are 256B-aligned)
    ull w[32];
    const ull* wrow = (const ull*)(Wmat + row * HD);
#pragma unroll
    for (int i2 = 0; i2 < 32; i2++) w[i2] = wrow[i2];
    const float bias = bvec[row];

    // task0 extras: layer0 input projection (IN=3)
    float wi0 = 0.f, wi1 = 0.f, wi2 = 0.f, bi = 0.f;
    if (task == 0) {
        wi0 = Wih0[row * 3 + 0];
        wi1 = Wih0[row * 3 + 1];
        wi2 = Wih0[row * 3 + 2];
        bi  = bih0[row];
    }

    for (int i2 = tid; i2 < NB * HD; i2 += NTH) {
        ((float*)p_state)[i2] = 0.f;
        ((float*)q_state)[i2] = 0.f;
    }
    // prefetch x for t = 0, 1
    if (tid < 2 * NB * 3) {
        int t = tid / (NB * 3);
        int rr = tid % (NB * 3);
        int b = rr / 3, f = rr % 3;
        xr[t][b][f] = x[(size_t)(b0 + b) * TT * 3 + t * 3 + f];
    }

    float hprev = 0.f;  // per-gate-thread recurrent lane
    __syncthreads();

    const float* src = (task == 2) ? &q_state[0][0] : &p_state[0][0];
    float* outarr = (task == 0) ? &h0s[0][0] : (task == 1) ? &a1s[0][0] : &h1s[0][0];

    for (int i = 0; i <= TT; i++) {
        const int sl = i & 3;

        // ---- phase 1: 64-wide dot per (row, b), batches in 2 halves ----
#pragma unroll
        for (int bh = 0; bh < 2; bh++) {
            const int ba = 2 * bh, bb = 2 * bh + 1;
            ull a00 = pack2(bias, 0.f), a01 = 0ull;
            ull a10 = pack2(bias, 0.f), a11 = 0ull;
            const ulonglong2* s0 = (const ulonglong2*)(src + ba * HD);
            const ulonglong2* s1 = (const ulonglong2*)(src + bb * HD);
#pragma unroll
            for (int k = 0; k < 16; k++) {
                ulonglong2 h0 = s0[k];
                fma2_acc(a00, h0.x, w[2 * k]);
                fma2_acc(a01, h0.y, w[2 * k + 1]);
                ulonglong2 h1 = s1[k];
                fma2_acc(a10, h1.x, w[2 * k]);
                fma2_acc(a11, h1.y, w[2 * k + 1]);
            }
            outarr[ba * GG + row] = hadd2(add2(a00, a01));
            outarr[bb * GG + row] = hadd2(add2(a10, a11));
        }
        if (task == 0) {
#pragma unroll
            for (int b = 0; b < NB; b++) {
                a0s[b][row] = fmaf(wi2, xr[sl][b][2],
                              fmaf(wi1, xr[sl][b][1],
                              fmaf(wi0, xr[sl][b][0], bi)));
            }
        }
        __syncthreads();

        // ---- phase 2: gates + prefetch ----
        if (tid < 256) {
            if (i < TT) {       // layer0 step t=i
                int b = tid >> 6, j = tid & 63;
                float r = sigf(a0s[b][j]      + h0s[b][j]);
                float z = sigf(a0s[b][j + 64] + h0s[b][j + 64]);
                float n = tanh_fast(fmaf(r, h0s[b][j + 128], a0s[b][j + 128]));
                float h = fmaf(z, hprev - n, n);
                hprev = h;
                p_state[b][j] = h;
            }
        } else if (tid < 512) {
            if (i >= 1) {       // layer1 step t=i-1
                int b = (tid - 256) >> 6, j = tid & 63;
                float r = sigf(a1s[b][j]      + h1s[b][j]);
                float z = sigf(a1s[b][j + 64] + h1s[b][j + 64]);
                float n = tanh_fast(fmaf(r, h1s[b][j + 128], a1s[b][j + 128]));
                float h = fmaf(z, hprev - n, n);
                hprev = h;
                q_state[b][j] = h;
                seq_out[((size_t)(b0 + b) * TT + (i - 1)) * HD + j] = h;
                if (i == TT) fin[(b0 + b) * HD + j] = h;
            }
        } else if (tid < 512 + NB * 3) {
            int t2 = i + 2;
            if (t2 < TT) {
                int rr = tid - 512;
                int b = rr / 3, f = rr % 3;
                xr[t2 & 3][b][f] = x[(size_t)(b0 + b) * TT * 3 + t2 * 3 + f];
            }
        }
        __syncthreads();
    }
}

// ---------------- launch ----------------

extern "C" void kernel_launch(void* const* d_in, const int* in_sizes, int n_in,
                              void* d_out, int out_size)
{
    const float* x    = (const float*)d_in[0];
    const float* Wih0 = (const float*)d_in[1];
    const float* Whh0 = (const float*)d_in[2];
    const float* bih0 = (const float*)d_in[3];
    const float* bhh0 = (const float*)d_in[4];
    const float* Wih1 = (const float*)d_in[5];
    const float* Whh1 = (const float*)d_in[6];
    const float* bih1 = (const float*)d_in[7];
    const float* bhh1 = (const float*)d_in[8];

    float* seq_out = (float*)d_out;
    float* fin     = seq_out + (size_t)BB * TT * HD;

    gru_fused<<<NCTA, NTH>>>(x, Wih0, Whh0, bih0, bhh0,
                             Wih1, Whh1, bih1, bhh1, seq_out, fin);
}